// round 14
// baseline (speedup 1.0000x reference)
#include <cuda_runtime.h>
#include <cstdint>

#define NB 4
#define NA (1 << 20)
#define BPB 256                      // scan blocks per batch
#define NBLOCKS (NB * BPB)           // 1024
#define NTHREADS 256
#define ROWS_PER_BLOCK (NA / BPB)    // 4096 rows (props) per block
#define QUADS_PER_THREAD (ROWS_PER_BLOCK / 4 / NTHREADS)  // 4

// 16 global slots: [group*2 + {0:top1, 1:top2}], group = batch*2 + class_col.
// Monotone under atomicMax within a run; pass2 resets them after snapshot,
// so every graph replay starts from zero -> deterministic.
__device__ unsigned long long g_slot[16];

__device__ __forceinline__ unsigned long long make_key(float v, unsigned int idx) {
    // high 32: float bits of positive score (order-preserving for positives)
    // low 32 : ~idx  (ties in score -> smaller index = larger key)
    return (((unsigned long long)__float_as_uint(v)) << 32) | (unsigned long long)(~idx);
}

__device__ __forceinline__ void upd2(unsigned long long& a1, unsigned long long& a2,
                                     unsigned long long k) {
    if (k > a1) { a2 = a1; a1 = k; }
    else if (k > a2) { a2 = k; }
}

// merge top-2 list (b1>=b2) into (a1>=a2)
__device__ __forceinline__ void merge2(unsigned long long& a1, unsigned long long& a2,
                                       unsigned long long b1, unsigned long long b2) {
    unsigned long long hi = a1 > b1 ? a1 : b1;
    unsigned long long lo = a1 > b1 ? b1 : a1;
    unsigned long long m2 = a2 > b2 ? a2 : b2;
    a1 = hi;
    a2 = lo > m2 ? lo : m2;
}

// Guarded exact top-2 insert (distinct keys within a run).
// Guard: slots only grow, so observing s[1] >= k proves k can never affect the
// final (top1, top2) -> skip with no atomic. Otherwise classic two-stage
// atomicMax: the displaced (or losing) value is handed atomically to exactly
// one thread which pushes it into s[1]; the true 2nd max always lands in s[1].
__device__ __forceinline__ void atomic_insert2_guarded(unsigned long long* s,
                                                       unsigned long long k) {
    if (*((volatile unsigned long long*)&s[1]) >= k) return;
    unsigned long long o = atomicMax(&s[0], k);
    unsigned long long r = o < k ? o : k;   // value pushed down to s[1]
    if (r) atomicMax(&s[1], r);
}

// Pass 1: proven LTS-cap top-2 scan; thread 0 inserts the block's 4 keys into
// the 16 global slots (guarded -> ~no contention). No fences, no election.
__global__ void __launch_bounds__(NTHREADS) pass1_top2(const float* __restrict__ probs) {
    const int tid   = threadIdx.x;
    const int blk   = blockIdx.x;
    const int batch = blk >> 8;        // / BPB
    const int chunk = blk & (BPB - 1);
    const long long row0 = (long long)batch * NA + (long long)chunk * ROWS_PER_BLOCK;
    const float4* __restrict__ p4 = reinterpret_cast<const float4*>(probs);

    unsigned long long k0a = 0, k0b = 0;  // class column 0 (cls=1)
    unsigned long long k1a = 0, k1b = 0;  // class column 1 (cls=2)

#pragma unroll
    for (int it = 0; it < QUADS_PER_THREAD; ++it) {
        const long long row = row0 + (long long)(it * NTHREADS + tid) * 4;
        const long long f4  = (row >> 2) * 3;  // row*3/4, row % 4 == 0
        const float4 A = p4[f4];
        const float4 B = p4[f4 + 1];
        const float4 C = p4[f4 + 2];
        // A = {r0c0,r0c1,r0c2,r1c0}, B = {r1c1,r1c2,r2c0,r2c1}, C = {r2c2,r3c0,r3c1,r3c2}
        const unsigned int i0 = (unsigned int)(row * 2);  // fg flat index of (row, col0)
        upd2(k0a, k0b, make_key(A.y, i0 + 0));
        upd2(k1a, k1b, make_key(A.z, i0 + 1));
        upd2(k0a, k0b, make_key(B.x, i0 + 2));
        upd2(k1a, k1b, make_key(B.y, i0 + 3));
        upd2(k0a, k0b, make_key(B.w, i0 + 4));
        upd2(k1a, k1b, make_key(C.x, i0 + 5));
        upd2(k0a, k0b, make_key(C.z, i0 + 6));
        upd2(k1a, k1b, make_key(C.w, i0 + 7));
    }

    __shared__ unsigned long long s[NTHREADS][4];
    s[tid][0] = k0a;
    s[tid][1] = k0b;
    s[tid][2] = k1a;
    s[tid][3] = k1b;
    __syncthreads();

    for (int off = NTHREADS / 2; off > 0; off >>= 1) {
        if (tid < off) {
            unsigned long long a1 = s[tid][0], a2 = s[tid][1];
            merge2(a1, a2, s[tid + off][0], s[tid + off][1]);
            s[tid][0] = a1; s[tid][1] = a2;
            unsigned long long c1 = s[tid][2], c2 = s[tid][3];
            merge2(c1, c2, s[tid + off][2], s[tid + off][3]);
            s[tid][2] = c1; s[tid][3] = c2;
        }
        __syncthreads();
    }

    if (tid == 0) {
        unsigned long long* g0 = &g_slot[(batch * 2 + 0) * 2];  // class col 0
        unsigned long long* g1 = &g_slot[(batch * 2 + 1) * 2];  // class col 1
        atomic_insert2_guarded(g0, s[0][0]);
        atomic_insert2_guarded(g0, s[0][1]);
        atomic_insert2_guarded(g1, s[0][2]);
        atomic_insert2_guarded(g1, s[0][3]);
    }
}

// Pass 2: ONE WARP. One 128B line of slots, shuffle rank sort (no smem, no
// syncthreads), 16 parallel decodes, reset slots for the next replay.
__global__ void __launch_bounds__(32) pass2_decode(const float* __restrict__ anchors,
                                                   const float* __restrict__ deltas,
                                                   float* __restrict__ out) {
    const int tid = threadIdx.x;

    unsigned long long key = 0;
    if (tid < 16) key = *((volatile unsigned long long*)&g_slot[tid]);

    // rank sort via shuffles: all 16 keys distinct (unique index in low bits)
    int rank = 0;
#pragma unroll
    for (int j = 0; j < 16; ++j) {
        unsigned long long kj = __shfl_sync(0xffffffffu, key, j);
        rank += (kj > key) ? 1 : 0;
    }

    if (tid < 16) {
        g_slot[tid] = 0ULL;                    // reset for the next replay

        const unsigned int flat = ~((unsigned int)key);        // fg flat index
        const int prop = (int)(flat >> 1);
        const int cls  = (int)(flat & 1u) + 1;
        const float score = __uint_as_float((unsigned int)(key >> 32));
        const int b_ix = prop >> 20;           // batch_ixs = repeat(arange(NB), NA)
        const int aidx = prop & (NA - 1);

        const float scale[6] = {256.f, 256.f, 256.f, 256.f, 128.f, 128.f};
        const float stdv[6]  = {0.1f, 0.1f, 0.1f, 0.2f, 0.2f, 0.2f};

        // vectorized gathers: rows are 6 floats = 24B, 8B-aligned -> 3x float2
        const float2* __restrict__ a2p = reinterpret_cast<const float2*>(anchors) +
                                         (long long)aidx * 3;
        const float2* __restrict__ d2p = reinterpret_cast<const float2*>(deltas) +
                                         (long long)prop * 3;
        const float2 av0 = a2p[0], av1 = a2p[1], av2 = a2p[2];
        const float2 dv0 = d2p[0], dv1 = d2p[1], dv2 = d2p[2];

        float anc[6] = {av0.x, av0.y, av1.x, av1.y, av2.x, av2.y};
        float dl [6] = {dv0.x, dv0.y, dv1.x, dv1.y, dv2.x, dv2.y};
#pragma unroll
        for (int j = 0; j < 6; ++j) anc[j] = floorf(anc[j] / scale[j]);
#pragma unroll
        for (int j = 0; j < 6; ++j) dl[j] *= stdv[j];

        float h = anc[2] - anc[0];
        float w = anc[3] - anc[1];
        float d = anc[5] - anc[4];
        float cy = anc[0] + 0.5f * h + dl[0] * h;
        float cx = anc[1] + 0.5f * w + dl[1] * w;
        float cz = anc[4] + 0.5f * d + dl[2] * d;
        h *= expf(dl[3]);
        w *= expf(dl[4]);
        d *= expf(dl[5]);

        float box[6];
        box[0] = cy - 0.5f * h;
        box[1] = cx - 0.5f * w;
        box[2] = box[0] + h;
        box[3] = box[1] + w;
        box[4] = cz - 0.5f * d;
        box[5] = box[4] + d;

        float* o = out + rank * 9;   // each thread writes its sorted slot
#pragma unroll
        for (int j = 0; j < 6; ++j)
            o[j] = rintf(fminf(fmaxf(box[j] * scale[j], 0.0f), scale[j]));
        o[6] = (float)b_ix;
        o[7] = (float)cls;
        o[8] = score;
    }
}

extern "C" void kernel_launch(void* const* d_in, const int* in_sizes, int n_in,
                              void* d_out, int out_size) {
    // identify inputs by element count (robust to ordering)
    const float* anchors = nullptr;   // NA*6       = 6,291,456
    const float* probs   = nullptr;   // NB*NA*3    = 12,582,912
    const float* deltas  = nullptr;   // NB*NA*6    = 25,165,824
    for (int i = 0; i < n_in; ++i) {
        switch (in_sizes[i]) {
            case 6291456:  anchors = (const float*)d_in[i]; break;
            case 12582912: probs   = (const float*)d_in[i]; break;
            case 25165824: deltas  = (const float*)d_in[i]; break;
            default: break;
        }
    }

    pass1_top2<<<NBLOCKS, NTHREADS>>>(probs);
    pass2_decode<<<1, 32>>>(anchors, deltas, (float*)d_out);
}

// round 15
// speedup vs baseline: 1.1047x; 1.1047x over previous
#include <cuda_runtime.h>
#include <cstdint>

#define NB 4
#define NA (1 << 20)
#define BPB 256                      // scan blocks per batch
#define NBLOCKS (NB * BPB)           // 1024
#define NTHREADS 256
#define ROWS_PER_BLOCK (NA / BPB)    // 4096 rows (props) per block
#define QUADS_PER_THREAD (ROWS_PER_BLOCK / 4 / NTHREADS)  // 4

// scratch: per block, 4 u64 keys: [col0_top1, col0_top2, col1_top1, col1_top2]
// Fully overwritten every run -> no reset, replay-deterministic.
__device__ unsigned long long g_scratch[NBLOCKS * 4];

__device__ __forceinline__ unsigned long long make_key(float v, unsigned int idx) {
    // high 32: float bits of positive score (order-preserving for positives)
    // low 32 : ~idx  (ties in score -> smaller index = larger key)
    return (((unsigned long long)__float_as_uint(v)) << 32) | (unsigned long long)(~idx);
}

__device__ __forceinline__ void upd2(unsigned long long& a1, unsigned long long& a2,
                                     unsigned long long k) {
    if (k > a1) { a2 = a1; a1 = k; }
    else if (k > a2) { a2 = k; }
}

// merge top-2 list (b1>=b2) into (a1>=a2)
__device__ __forceinline__ void merge2(unsigned long long& a1, unsigned long long& a2,
                                       unsigned long long b1, unsigned long long b2) {
    unsigned long long hi = a1 > b1 ? a1 : b1;
    unsigned long long lo = a1 > b1 ? b1 : a1;
    unsigned long long m2 = a2 > b2 ? a2 : b2;
    a1 = hi;
    a2 = lo > m2 ? lo : m2;
}

// Pass 1: proven top-2 scan, now with pure 32-bit index arithmetic
// (row <= 4.2M, f4 <= 3.1M, i0 <= 8.4M all fit u32) to cut the 64-bit
// IMAD chains contending with the u64 compare chains on the ALU pipe.
__global__ void __launch_bounds__(NTHREADS) pass1_top2(const float* __restrict__ probs) {
    const int tid   = threadIdx.x;
    const int blk   = blockIdx.x;
    const int batch = blk >> 8;        // / BPB
    const int chunk = blk & (BPB - 1);
    const unsigned int row0 = (unsigned int)batch * NA + (unsigned int)chunk * ROWS_PER_BLOCK;
    const float4* __restrict__ p4 = reinterpret_cast<const float4*>(probs);

    unsigned long long k0a = 0, k0b = 0;  // class column 0 (cls=1)
    unsigned long long k1a = 0, k1b = 0;  // class column 1 (cls=2)

#pragma unroll
    for (int it = 0; it < QUADS_PER_THREAD; ++it) {
        const unsigned int row = row0 + (unsigned int)(it * NTHREADS + tid) * 4u;
        const unsigned int f4  = (row >> 2) * 3u;  // row*3/4, row % 4 == 0
        const float4 A = p4[f4];
        const float4 B = p4[f4 + 1];
        const float4 C = p4[f4 + 2];
        // A = {r0c0,r0c1,r0c2,r1c0}, B = {r1c1,r1c2,r2c0,r2c1}, C = {r2c2,r3c0,r3c1,r3c2}
        const unsigned int i0 = row * 2u;  // fg flat index of (row, col0)
        upd2(k0a, k0b, make_key(A.y, i0 + 0));
        upd2(k1a, k1b, make_key(A.z, i0 + 1));
        upd2(k0a, k0b, make_key(B.x, i0 + 2));
        upd2(k1a, k1b, make_key(B.y, i0 + 3));
        upd2(k0a, k0b, make_key(B.w, i0 + 4));
        upd2(k1a, k1b, make_key(C.x, i0 + 5));
        upd2(k0a, k0b, make_key(C.z, i0 + 6));
        upd2(k1a, k1b, make_key(C.w, i0 + 7));
    }

    __shared__ unsigned long long s[NTHREADS][4];
    s[tid][0] = k0a;
    s[tid][1] = k0b;
    s[tid][2] = k1a;
    s[tid][3] = k1b;
    __syncthreads();

    for (int off = NTHREADS / 2; off > 0; off >>= 1) {
        if (tid < off) {
            unsigned long long a1 = s[tid][0], a2 = s[tid][1];
            merge2(a1, a2, s[tid + off][0], s[tid + off][1]);
            s[tid][0] = a1; s[tid][1] = a2;
            unsigned long long c1 = s[tid][2], c2 = s[tid][3];
            merge2(c1, c2, s[tid + off][2], s[tid + off][3]);
            s[tid][2] = c1; s[tid][3] = c2;
        }
        __syncthreads();
    }

    if (tid == 0) {
#pragma unroll
        for (int j = 0; j < 4; ++j) g_scratch[blk * 4 + j] = s[0][j];
    }
}

// Pass 2: 128 threads / 4 warps. Warp w = batch w; lanes 0-15 merge class
// col 0 (16 blocks each via ulonglong2 loads, MLP 16, L2-hot), lanes 16-31
// class col 1. Half-warp shuffle reduce -> 16 group keys -> rank sort -> decode.
__global__ void __launch_bounds__(128) pass2_decode(const float* __restrict__ anchors,
                                                    const float* __restrict__ deltas,
                                                    float* __restrict__ out) {
    const int tid  = threadIdx.x;
    const int warp = tid >> 5;        // batch
    const int lane = tid & 31;
    const int col  = lane >> 4;       // 0: cls=1, 1: cls=2
    const int sub  = lane & 15;       // 16-way split of the 256 blocks

    __shared__ unsigned long long gtop[16];

    {
        unsigned long long a1 = 0, a2 = 0;
        const ulonglong2* __restrict__ sc2 =
            reinterpret_cast<const ulonglong2*>(g_scratch);
        // block blk keys for (batch,col) live at g_scratch[blk*4 + col*2 + {0,1}]
        // = ulonglong2 index blk*2 + col
        const int base = (warp * BPB + sub * 16) * 2 + col;
#pragma unroll
        for (int b = 0; b < 16; ++b) {
            const ulonglong2 v = sc2[base + b * 2];
            merge2(a1, a2, v.x, v.y);
        }
        // reduce across the 16 lanes of this half-warp
#pragma unroll
        for (int off = 8; off > 0; off >>= 1) {
            unsigned long long b1 = __shfl_down_sync(0xffffffffu, a1, off);
            unsigned long long b2 = __shfl_down_sync(0xffffffffu, a2, off);
            merge2(a1, a2, b1, b2);
        }
        if (sub == 0) {
            const int g = warp * 2 + col;
            gtop[g * 2]     = a1;
            gtop[g * 2 + 1] = a2;
        }
    }
    __syncthreads();

    if (tid < 16) {
        // rank sort: all 16 keys distinct (unique fg flat index in low bits)
        const unsigned long long key = gtop[tid];
        int rank = 0;
#pragma unroll
        for (int j = 0; j < 16; ++j) rank += (gtop[j] > key) ? 1 : 0;

        const unsigned int flat = ~((unsigned int)key);        // fg flat index
        const int prop = (int)(flat >> 1);
        const int cls  = (int)(flat & 1u) + 1;
        const float score = __uint_as_float((unsigned int)(key >> 32));
        const int b_ix = prop >> 20;           // batch_ixs = repeat(arange(NB), NA)
        const int aidx = prop & (NA - 1);

        const float scale[6] = {256.f, 256.f, 256.f, 256.f, 128.f, 128.f};
        const float stdv[6]  = {0.1f, 0.1f, 0.1f, 0.2f, 0.2f, 0.2f};

        // vectorized gathers: rows are 6 floats = 24B, 8B-aligned -> 3x float2
        const float2* __restrict__ a2p = reinterpret_cast<const float2*>(anchors) +
                                         (long long)aidx * 3;
        const float2* __restrict__ d2p = reinterpret_cast<const float2*>(deltas) +
                                         (long long)prop * 3;
        const float2 av0 = a2p[0], av1 = a2p[1], av2 = a2p[2];
        const float2 dv0 = d2p[0], dv1 = d2p[1], dv2 = d2p[2];

        float anc[6] = {av0.x, av0.y, av1.x, av1.y, av2.x, av2.y};
        float dl [6] = {dv0.x, dv0.y, dv1.x, dv1.y, dv2.x, dv2.y};
#pragma unroll
        for (int j = 0; j < 6; ++j) anc[j] = floorf(anc[j] / scale[j]);
#pragma unroll
        for (int j = 0; j < 6; ++j) dl[j] *= stdv[j];

        float h = anc[2] - anc[0];
        float w = anc[3] - anc[1];
        float d = anc[5] - anc[4];
        float cy = anc[0] + 0.5f * h + dl[0] * h;
        float cx = anc[1] + 0.5f * w + dl[1] * w;
        float cz = anc[4] + 0.5f * d + dl[2] * d;
        h *= expf(dl[3]);
        w *= expf(dl[4]);
        d *= expf(dl[5]);

        float box[6];
        box[0] = cy - 0.5f * h;
        box[1] = cx - 0.5f * w;
        box[2] = box[0] + h;
        box[3] = box[1] + w;
        box[4] = cz - 0.5f * d;
        box[5] = box[4] + d;

        float* o = out + rank * 9;   // each thread writes its sorted slot
#pragma unroll
        for (int j = 0; j < 6; ++j)
            o[j] = rintf(fminf(fmaxf(box[j] * scale[j], 0.0f), scale[j]));
        o[6] = (float)b_ix;
        o[7] = (float)cls;
        o[8] = score;
    }
}

extern "C" void kernel_launch(void* const* d_in, const int* in_sizes, int n_in,
                              void* d_out, int out_size) {
    // identify inputs by element count (robust to ordering)
    const float* anchors = nullptr;   // NA*6       = 6,291,456
    const float* probs   = nullptr;   // NB*NA*3    = 12,582,912
    const float* deltas  = nullptr;   // NB*NA*6    = 25,165,824
    for (int i = 0; i < n_in; ++i) {
        switch (in_sizes[i]) {
            case 6291456:  anchors = (const float*)d_in[i]; break;
            case 12582912: probs   = (const float*)d_in[i]; break;
            case 25165824: deltas  = (const float*)d_in[i]; break;
            default: break;
        }
    }

    pass1_top2<<<NBLOCKS, NTHREADS>>>(probs);
    pass2_decode<<<1, 128>>>(anchors, deltas, (float*)d_out);
}

// round 16
// speedup vs baseline: 1.2521x; 1.1335x over previous
#include <cuda_runtime.h>
#include <cstdint>

#define NB 4
#define NA (1 << 20)
#define BPB 256                      // scan blocks per batch
#define NBLOCKS (NB * BPB)           // 1024 (power of 2 -> monotonic election works)
#define NTHREADS 256
#define ROWS_PER_BLOCK (NA / BPB)    // 4096 rows (props) per block
#define QUADS_PER_THREAD (ROWS_PER_BLOCK / 4 / NTHREADS)  // 4

// scratch: per block, 4 u64 keys: [col0_top1, col0_top2, col1_top1, col1_top2]
// Fully overwritten every run -> no reset needed.
__device__ unsigned long long g_scratch[NBLOCKS * 4];
__device__ unsigned int g_count = 0;   // monotonic across graph replays

__device__ __forceinline__ unsigned int atomic_add_release_gpu(unsigned int* p,
                                                               unsigned int v) {
    unsigned int old;
    asm volatile("atom.release.gpu.global.add.u32 %0, [%1], %2;"
                 : "=r"(old) : "l"(p), "r"(v) : "memory");
    return old;
}

__device__ __forceinline__ unsigned int ld_acquire_gpu(unsigned int* p) {
    unsigned int v;
    asm volatile("ld.acquire.gpu.global.u32 %0, [%1];"
                 : "=r"(v) : "l"(p) : "memory");
    return v;
}

__device__ __forceinline__ unsigned long long make_key(float v, unsigned int idx) {
    // high 32: float bits of positive score (order-preserving for positives)
    // low 32 : ~idx  (ties in score -> smaller index = larger key)
    return (((unsigned long long)__float_as_uint(v)) << 32) | (unsigned long long)(~idx);
}

__device__ __forceinline__ void upd2(unsigned long long& a1, unsigned long long& a2,
                                     unsigned long long k) {
    if (k > a1) { a2 = a1; a1 = k; }
    else if (k > a2) { a2 = k; }
}

// merge top-2 list (b1>=b2) into (a1>=a2)
__device__ __forceinline__ void merge2(unsigned long long& a1, unsigned long long& a2,
                                       unsigned long long b1, unsigned long long b2) {
    unsigned long long hi = a1 > b1 ? a1 : b1;
    unsigned long long lo = a1 > b1 ? b1 : a1;
    unsigned long long m2 = a2 > b2 ? a2 : b2;
    a1 = hi;
    a2 = lo > m2 ? lo : m2;
}

// Fused: proven R5 scan + ONE release-atomic per block (no __threadfence
// anywhere -> no CCTL.IVALL storm) + elected last block runs the tail.
__global__ void __launch_bounds__(NTHREADS)
fused_top2_decode(const float* __restrict__ probs,
                  const float* __restrict__ anchors,
                  const float* __restrict__ deltas,
                  float* __restrict__ out) {
    const int tid   = threadIdx.x;
    const int blk   = blockIdx.x;
    const int batch = blk >> 8;        // / BPB
    const int chunk = blk & (BPB - 1);
    const long long row0 = (long long)batch * NA + (long long)chunk * ROWS_PER_BLOCK;
    const float4* __restrict__ p4 = reinterpret_cast<const float4*>(probs);

    unsigned long long k0a = 0, k0b = 0;  // class column 0 (cls=1)
    unsigned long long k1a = 0, k1b = 0;  // class column 1 (cls=2)

#pragma unroll
    for (int it = 0; it < QUADS_PER_THREAD; ++it) {
        const long long row = row0 + (long long)(it * NTHREADS + tid) * 4;
        const long long f4  = (row >> 2) * 3;  // row*3/4, row % 4 == 0
        const float4 A = p4[f4];
        const float4 B = p4[f4 + 1];
        const float4 C = p4[f4 + 2];
        // A = {r0c0,r0c1,r0c2,r1c0}, B = {r1c1,r1c2,r2c0,r2c1}, C = {r2c2,r3c0,r3c1,r3c2}
        const unsigned int i0 = (unsigned int)(row * 2);  // fg flat index of (row, col0)
        upd2(k0a, k0b, make_key(A.y, i0 + 0));
        upd2(k1a, k1b, make_key(A.z, i0 + 1));
        upd2(k0a, k0b, make_key(B.x, i0 + 2));
        upd2(k1a, k1b, make_key(B.y, i0 + 3));
        upd2(k0a, k0b, make_key(B.w, i0 + 4));
        upd2(k1a, k1b, make_key(C.x, i0 + 5));
        upd2(k0a, k0b, make_key(C.z, i0 + 6));
        upd2(k1a, k1b, make_key(C.w, i0 + 7));
    }

    __shared__ unsigned long long s[NTHREADS][4];
    s[tid][0] = k0a;
    s[tid][1] = k0b;
    s[tid][2] = k1a;
    s[tid][3] = k1b;
    __syncthreads();

    for (int off = NTHREADS / 2; off > 0; off >>= 1) {
        if (tid < off) {
            unsigned long long a1 = s[tid][0], a2 = s[tid][1];
            merge2(a1, a2, s[tid + off][0], s[tid + off][1]);
            s[tid][0] = a1; s[tid][1] = a2;
            unsigned long long c1 = s[tid][2], c2 = s[tid][3];
            merge2(c1, c2, s[tid + off][2], s[tid + off][3]);
            s[tid][2] = c1; s[tid][3] = c2;
        }
        __syncthreads();
    }

    // ---- publish + election: ONE release-atomic by thread 0 only ----
    __shared__ bool isLast;
    if (tid == 0) {
#pragma unroll
        for (int j = 0; j < 4; ++j) g_scratch[blk * 4 + j] = s[0][j];
        // release orders the scratch stores before the counter increment
        unsigned int old = atomic_add_release_gpu(&g_count, 1u);
        isLast = (((old + 1) & (NBLOCKS - 1)) == 0);
        if (isLast) (void)ld_acquire_gpu(&g_count);  // acquire: see all scratch
    }
    __syncthreads();   // CTA barrier publishes the acquired view block-wide
    if (!isLast) return;

    // ---- tail: 8 warps reduce 8 groups; rank sort; decode; write 16x9 ----
    __shared__ unsigned long long gtop[16];
    const int warp = tid >> 5;
    const int lane = tid & 31;
    {
        const int gbatch = warp >> 1;
        const int col    = warp & 1;
        unsigned long long a1 = 0, a2 = 0;
#pragma unroll
        for (int b = 0; b < BPB / 32; ++b) {
            const int sblk = gbatch * BPB + b * 32 + lane;
            merge2(a1, a2, g_scratch[sblk * 4 + col * 2], g_scratch[sblk * 4 + col * 2 + 1]);
        }
#pragma unroll
        for (int off = 16; off > 0; off >>= 1) {
            unsigned long long b1 = __shfl_down_sync(0xffffffffu, a1, off);
            unsigned long long b2 = __shfl_down_sync(0xffffffffu, a2, off);
            merge2(a1, a2, b1, b2);
        }
        if (lane == 0) { gtop[warp * 2] = a1; gtop[warp * 2 + 1] = a2; }
    }
    __syncthreads();

    if (tid < 16) {
        // rank sort: all 16 keys distinct (unique fg flat index in low bits)
        const unsigned long long key = gtop[tid];
        int rank = 0;
#pragma unroll
        for (int j = 0; j < 16; ++j) rank += (gtop[j] > key) ? 1 : 0;

        const unsigned int flat = ~((unsigned int)key);        // fg flat index
        const int prop = (int)(flat >> 1);
        const int cls  = (int)(flat & 1u) + 1;
        const float score = __uint_as_float((unsigned int)(key >> 32));
        const int b_ix = prop >> 20;           // batch_ixs = repeat(arange(NB), NA)
        const int aidx = prop & (NA - 1);

        const float scale[6] = {256.f, 256.f, 256.f, 256.f, 128.f, 128.f};
        const float stdv[6]  = {0.1f, 0.1f, 0.1f, 0.2f, 0.2f, 0.2f};

        // vectorized gathers: rows are 6 floats = 24B, 8B-aligned -> 3x float2
        const float2* __restrict__ a2p = reinterpret_cast<const float2*>(anchors) +
                                         (long long)aidx * 3;
        const float2* __restrict__ d2p = reinterpret_cast<const float2*>(deltas) +
                                         (long long)prop * 3;
        const float2 av0 = a2p[0], av1 = a2p[1], av2 = a2p[2];
        const float2 dv0 = d2p[0], dv1 = d2p[1], dv2 = d2p[2];

        float anc[6] = {av0.x, av0.y, av1.x, av1.y, av2.x, av2.y};
        float dl [6] = {dv0.x, dv0.y, dv1.x, dv1.y, dv2.x, dv2.y};
#pragma unroll
        for (int j = 0; j < 6; ++j) anc[j] = floorf(anc[j] / scale[j]);
#pragma unroll
        for (int j = 0; j < 6; ++j) dl[j] *= stdv[j];

        float h = anc[2] - anc[0];
        float w = anc[3] - anc[1];
        float d = anc[5] - anc[4];
        float cy = anc[0] + 0.5f * h + dl[0] * h;
        float cx = anc[1] + 0.5f * w + dl[1] * w;
        float cz = anc[4] + 0.5f * d + dl[2] * d;
        h *= expf(dl[3]);
        w *= expf(dl[4]);
        d *= expf(dl[5]);

        float box[6];
        box[0] = cy - 0.5f * h;
        box[1] = cx - 0.5f * w;
        box[2] = box[0] + h;
        box[3] = box[1] + w;
        box[4] = cz - 0.5f * d;
        box[5] = box[4] + d;

        float* o = out + rank * 9;   // each thread writes its sorted slot
#pragma unroll
        for (int j = 0; j < 6; ++j)
            o[j] = rintf(fminf(fmaxf(box[j] * scale[j], 0.0f), scale[j]));
        o[6] = (float)b_ix;
        o[7] = (float)cls;
        o[8] = score;
    }
}

extern "C" void kernel_launch(void* const* d_in, const int* in_sizes, int n_in,
                              void* d_out, int out_size) {
    // identify inputs by element count (robust to ordering)
    const float* anchors = nullptr;   // NA*6       = 6,291,456
    const float* probs   = nullptr;   // NB*NA*3    = 12,582,912
    const float* deltas  = nullptr;   // NB*NA*6    = 25,165,824
    for (int i = 0; i < n_in; ++i) {
        switch (in_sizes[i]) {
            case 6291456:  anchors = (const float*)d_in[i]; break;
            case 12582912: probs   = (const float*)d_in[i]; break;
            case 25165824: deltas  = (const float*)d_in[i]; break;
            default: break;
        }
    }

    fused_top2_decode<<<NBLOCKS, NTHREADS>>>(probs, anchors, deltas, (float*)d_out);
}